// round 16
// baseline (speedup 1.0000x reference)
#include <cuda_runtime.h>

// TAHE: masked cosine-similarity weighted pooling — two-KERNEL split.
// K1: w[b,l] = [ts>0] * (cos(cur_n[b], rec[b,l])+1)/2   (reads rec only, no acc deps)
// K2: out[b,:] = sum_l w[b,l] * items[b,l,:]            (pure stream, FMA-only carries)
// B=4096, L=200, D=128 f32. ~50% rows masked -> their 512B rows never loaded.

#define TB 4096
#define TL 200
#define TD 128
#define WARPS 8
#define TEPS 1e-12f

__device__ float g_wbuf[TB * TL];   // 3.3 MB scratch (static: allocation rules)

// ---------------------------------------------------------------- K1: weights
__global__ __launch_bounds__(WARPS * 32, 1)
void tahe_weights_kernel(const float* __restrict__ rec,
                         const float* __restrict__ cur,
                         const int*   __restrict__ ts)
{
    const int b      = blockIdx.x;
    const int tid    = threadIdx.x;
    const int wid    = tid >> 5;
    const int lane   = tid & 31;
    const int half   = lane >> 4;
    const int lane16 = lane & 15;

    __shared__ int   tss[TL];
    __shared__ float wsm[TL];

    if (tid < TL) tss[tid] = __ldg(&ts[(size_t)b * TL + tid]);

    // normalize cur[b,:] (redundant per warp, L1-resident)
    const float4* cur4 = reinterpret_cast<const float4*>(cur + (size_t)b * TD);
    float4 c = __ldg(&cur4[lane]);
    float ssum = c.x*c.x + c.y*c.y + c.z*c.z + c.w*c.w;
    #pragma unroll
    for (int o = 16; o > 0; o >>= 1)
        ssum += __shfl_xor_sync(0xffffffffu, ssum, o);
    const float rn = rsqrtf(fmaxf(ssum, TEPS));
    c.x *= rn; c.y *= rn; c.z *= rn; c.w *= rn;

    // lane needs normalized cur float4s lane16 and lane16+16 (16-lane row layout)
    float4 c0, c1;
    c0.x = __shfl_sync(0xffffffffu, c.x, lane16);
    c0.y = __shfl_sync(0xffffffffu, c.y, lane16);
    c0.z = __shfl_sync(0xffffffffu, c.z, lane16);
    c0.w = __shfl_sync(0xffffffffu, c.w, lane16);
    c1.x = __shfl_sync(0xffffffffu, c.x, lane16 + 16);
    c1.y = __shfl_sync(0xffffffffu, c.y, lane16 + 16);
    c1.z = __shfl_sync(0xffffffffu, c.z, lane16 + 16);
    c1.w = __shfl_sync(0xffffffffu, c.w, lane16 + 16);

    __syncthreads();

    const float4* rec4 = reinterpret_cast<const float4*>(rec + (size_t)b * TL * TD);

    // group g = 2*wid+half owns rows g, g+16, g+32, ... ; 2 rows per iteration
    // (rows rA = g+32k, rB = g+16+32k) -> 4 independent butterfly chains per warp.
    const int g = 2 * wid + half;
    for (int k = g; k < TL; k += 32) {
        const int rA = k;            // g + 32*i
        const int rB = k + 16;       // may be >= TL on the tail
        const int mA = tss[rA];
        const int mB = (rB < TL) ? tss[rB] : 0;

        float4 ra0 = make_float4(0.f,0.f,0.f,0.f), ra1 = make_float4(0.f,0.f,0.f,0.f);
        float4 rb0 = make_float4(0.f,0.f,0.f,0.f), rb1 = make_float4(0.f,0.f,0.f,0.f);

        if (mA > 0) {
            ra0 = __ldg(&rec4[rA * 32 + lane16]);
            ra1 = __ldg(&rec4[rA * 32 + 16 + lane16]);
        }
        if (mB > 0) {
            rb0 = __ldg(&rec4[rB * 32 + lane16]);
            rb1 = __ldg(&rec4[rB * 32 + 16 + lane16]);
        }

        float dotA = ra0.x*c0.x + ra0.y*c0.y + ra0.z*c0.z + ra0.w*c0.w
                   + ra1.x*c1.x + ra1.y*c1.y + ra1.z*c1.z + ra1.w*c1.w;
        float sqA  = ra0.x*ra0.x + ra0.y*ra0.y + ra0.z*ra0.z + ra0.w*ra0.w
                   + ra1.x*ra1.x + ra1.y*ra1.y + ra1.z*ra1.z + ra1.w*ra1.w;
        float dotB = rb0.x*c0.x + rb0.y*c0.y + rb0.z*c0.z + rb0.w*c0.w
                   + rb1.x*c1.x + rb1.y*c1.y + rb1.z*c1.z + rb1.w*c1.w;
        float sqB  = rb0.x*rb0.x + rb0.y*rb0.y + rb0.z*rb0.z + rb0.w*rb0.w
                   + rb1.x*rb1.x + rb1.y*rb1.y + rb1.z*rb1.z + rb1.w*rb1.w;

        // 4-level butterfly within 16-lane groups; unconditional full warp (offsets <=8
        // never cross the group boundary; zero-filled regs make masked rows harmless).
        #pragma unroll
        for (int o = 8; o > 0; o >>= 1) {
            dotA += __shfl_xor_sync(0xffffffffu, dotA, o);
            sqA  += __shfl_xor_sync(0xffffffffu, sqA,  o);
            dotB += __shfl_xor_sync(0xffffffffu, dotB, o);
            sqB  += __shfl_xor_sync(0xffffffffu, sqB,  o);
        }

        if (lane16 == 0) {
            wsm[rA] = (mA > 0) ? (dotA * rsqrtf(fmaxf(sqA, TEPS)) + 1.0f) * 0.5f : 0.0f;
            if (rB < TL)
                wsm[rB] = (mB > 0) ? (dotB * rsqrtf(fmaxf(sqB, TEPS)) + 1.0f) * 0.5f : 0.0f;
        }
    }
    __syncthreads();

    if (tid < TL) g_wbuf[(size_t)b * TL + tid] = wsm[tid];
}

// ------------------------------------------------------------------- K2: pool
__global__ __launch_bounds__(WARPS * 32, 1)
void tahe_pool_kernel(const float* __restrict__ items,
                      float*       __restrict__ out)
{
    const int b    = blockIdx.x;
    const int tid  = threadIdx.x;
    const int wid  = tid >> 5;
    const int lane = tid & 31;

    __shared__ float  wsm[TL];
    __shared__ float4 red[WARPS][32];

    if (tid < TL) wsm[tid] = g_wbuf[(size_t)b * TL + tid];
    __syncthreads();

    const float4* it4 = reinterpret_cast<const float4*>(items + (size_t)b * TL * TD);

    float4 acc = make_float4(0.f, 0.f, 0.f, 0.f);

    #pragma unroll 5
    for (int l = wid; l < TL; l += WARPS) {
        const float w = wsm[l];
        if (w != 0.0f) {
            const float4 v = __ldg(&it4[l * 32 + lane]);
            acc.x += w * v.x;
            acc.y += w * v.y;
            acc.z += w * v.z;
            acc.w += w * v.w;
        }
    }

    red[wid][lane] = acc;
    __syncthreads();

    if (wid == 0) {
        float4 s = red[0][lane];
        #pragma unroll
        for (int w = 1; w < WARPS; ++w) {
            const float4 t = red[w][lane];
            s.x += t.x; s.y += t.y; s.z += t.z; s.w += t.w;
        }
        reinterpret_cast<float4*>(out + (size_t)b * TD)[lane] = s;
    }
}

extern "C" void kernel_launch(void* const* d_in, const int* in_sizes, int n_in,
                              void* d_out, int out_size)
{
    const float* rec   = (const float*)d_in[0]; // recentTimeRepresentations [B,L,D]
    const float* cur   = (const float*)d_in[1]; // curTimeRepresentation    [B,D]
    const int*   ts    = (const int*)  d_in[2]; // recentTimestamps         [B,L]
    const float* items = (const float*)d_in[3]; // recentItemEmbeddings     [B,L,D]
    float*       out   = (float*)d_out;         // [B,D]

    tahe_weights_kernel<<<TB, WARPS * 32>>>(rec, cur, ts);
    tahe_pool_kernel   <<<TB, WARPS * 32>>>(items, out);
}